// round 6
// baseline (speedup 1.0000x reference)
#include <cuda_runtime.h>

#define NTYPES 4
#define NDESC  8
#define KMAX   8
#define LMAX   4
#define MNBR   20
#define RCUT   5.0f
#define PI_F   3.14159265358979f

#define WPB     4                    // warps per block (small blocks: finer waves, higher occ)
#define THREADS (WPB * 32)
#define CT_ROWS   (NTYPES * NTYPES)
#define CT_STRIDE 68                 // 68 % 32 == 4 -> conflict-free across type rows
#define REC_F4    7                  // edge record: 6 float4 used + 1 pad (STS conflict-free)
#define REC_F     (REC_F4 * 4)

__global__ __launch_bounds__(THREADS)
void angular_desc_kernel(const int*   __restrict__ types,
                         const float* __restrict__ positions,
                         const int*   __restrict__ nbrs,
                         const float* __restrict__ c_table,
                         float*       __restrict__ out,
                         int N)
{
    __shared__ float  sh_ct[CT_ROWS * CT_STRIDE];
    __shared__ float4 sh_e[WPB][MNBR][REC_F4];

    const int tid = threadIdx.x;

    // Stage c_table into padded shared (block-wide, once)
    for (int idx = tid; idx < CT_ROWS * 64; idx += THREADS) {
        int row = idx >> 6, col = idx & 63;
        sh_ct[row * CT_STRIDE + col] = c_table[idx];
    }
    __syncthreads();

    const int warp = tid >> 5;
    const int lane = tid & 31;
    const int atom = blockIdx.x * WPB + warp;
    if (atom >= N) return;

    const int   ti  = types[atom];
    const float pix = positions[atom * 3 + 0];
    const float piy = positions[atom * 3 + 1];
    const float piz = positions[atom * 3 + 2];

    // ---- Phase 1: per-edge records (lanes 0..19): g[8] and Z[16] ----
    if (lane < MNBR) {
        int j = nbrs[atom * MNBR + lane];
        float dx = positions[j * 3 + 0] - pix;
        float dy = positions[j * 3 + 1] - piy;
        float dz = positions[j * 3 + 2] - piz;
        int  tj = types[j];

        float n2  = dx * dx + dy * dy + dz * dz;
        float inv = rsqrtf(n2);
        float r   = n2 * inv;
        float x = dx * inv, y = dy * inv, z = dz * inv;

        // Chebyshev radial basis: f_k = (T_k(xc)+1) * 0.5*fc(r)
        float fc  = (r < RCUT) ? (0.5f * __cosf(PI_F * r * (1.0f / RCUT)) + 0.5f) : 0.0f;
        float hfc = 0.5f * fc;
        float xr  = r * (1.0f / RCUT) - 1.0f;
        float xc  = 2.0f * xr * xr - 1.0f;
        float fvec[KMAX];
        float tm2 = 1.0f, tm1 = xc;
        fvec[0] = (tm2 + 1.0f) * hfc;
        fvec[1] = (tm1 + 1.0f) * hfc;
        #pragma unroll
        for (int k = 2; k < KMAX; k++) {
            float t = 2.0f * xc * tm1 - tm2;
            tm2 = tm1; tm1 = t;
            fvec[k] = (t + 1.0f) * hfc;
        }

        const float* crow = &sh_ct[(ti * NTYPES + tj) * CT_STRIDE];
        float g[NDESC];
        #pragma unroll
        for (int d = 0; d < NDESC; d++) {
            const float4 c0 = *(const float4*)(crow + d * 8);
            const float4 c1 = *(const float4*)(crow + d * 8 + 4);
            g[d] = c0.x * fvec[0] + c0.y * fvec[1] + c0.z * fvec[2] + c0.w * fvec[3]
                 + c1.x * fvec[4] + c1.y * fvec[5] + c1.z * fvec[6] + c1.w * fvec[7];
        }

        // Real spherical harmonics Z_lm scaled so P_l(u.v) = sum_m Z_lm(u) Z_lm(v)
        float x2 = x * x, y2 = y * y, z2 = z * z;
        const float SQ3  = 1.73205080757f;
        const float SQ3H = 0.86602540378f;
        const float C31  = 0.61237243570f;   // sqrt(6)/4
        const float C32a = 3.87298334621f;   // sqrt(15)
        const float C32b = 1.93649167310f;   // sqrt(15)/2
        const float C33  = 0.79056941504f;   // sqrt(10)/4
        float a5z = 5.0f * z2 - 1.0f;

        sh_e[warp][lane][0] = make_float4(g[0], g[1], g[2], g[3]);
        sh_e[warp][lane][1] = make_float4(g[4], g[5], g[6], g[7]);
        sh_e[warp][lane][2] = make_float4(1.0f, x, y, z);
        sh_e[warp][lane][3] = make_float4(SQ3 * x * y, SQ3 * y * z, SQ3 * x * z, SQ3H * (x2 - y2));
        sh_e[warp][lane][4] = make_float4(0.5f * (3.0f * z2 - 1.0f),
                                          C33 * y * (3.0f * x2 - y2),
                                          C32a * x * y * z,
                                          C31 * y * a5z);
        sh_e[warp][lane][5] = make_float4(0.5f * z * (5.0f * z2 - 3.0f),
                                          C31 * x * a5z,
                                          C32b * z * (x2 - y2),
                                          C33 * x * (x2 - 3.0f * y2));
    }
    __syncwarp();

    // ---- Phase 2: S[d][m] = sum_j g_d(j) Z_m(j). lane: d = lane&7, mgroup = lane>>3 ----
    const int d  = lane & 7;
    const int mg = lane >> 3;
    const float* rec = (const float*)&sh_e[warp][0][0];

    float S0 = 0.0f, S1 = 0.0f, S2 = 0.0f, S3 = 0.0f, gg = 0.0f;
    #pragma unroll
    for (int jb = 0; jb < MNBR; jb += 4) {
        float  gv[4];
        float4 zv[4];
        #pragma unroll
        for (int u = 0; u < 4; u++) {
            const float* base = rec + (jb + u) * REC_F;
            gv[u] = base[d];                              // broadcast within d-group
            zv[u] = *(const float4*)(base + 8 + 4 * mg);  // 4 distinct 16B: conflict-free
        }
        #pragma unroll
        for (int u = 0; u < 4; u++) {
            S0 = fmaf(gv[u], zv[u].x, S0);
            S1 = fmaf(gv[u], zv[u].y, S1);
            S2 = fmaf(gv[u], zv[u].z, S2);
            S3 = fmaf(gv[u], zv[u].w, S3);
            gg = fmaf(gv[u], gv[u], gg);
        }
    }

    // Sums of squares split by l within each m-group:
    // mg0: m0(l0) | m1..3(l1);  mg1: m4..7(l2);  mg2: m8(l2) | m9..11(l3);  mg3: m12..15(l3)
    float PA, PB;
    if (mg == 0 || mg == 2) {
        PA = S0 * S0;
        PB = S1 * S1 + S2 * S2 + S3 * S3;
    } else {
        PA = S0 * S0 + S1 * S1 + S2 * S2 + S3 * S3;
        PB = 0.0f;
    }

    // ---- Phase 3: recombine to output lane (od = lane>>2, lo = lane&3) ----
    const int lo = lane & 3;
    const int od = lane >> 2;

    int srcA = (lo == 0) ? od : (lo == 2) ? (8 + od) : (lo == 3) ? (24 + od) : od;
    float vA = __shfl_sync(0xffffffffu, PA, srcA);
    int srcB = (lo == 1) ? od : (16 + od);
    float vB = __shfl_sync(0xffffffffu, PB, srcB);
    float vC = __shfl_sync(0xffffffffu, PA, 16 + od);
    float ggv = __shfl_sync(0xffffffffu, gg, od);

    float sumsq;
    if      (lo == 0) sumsq = vA;
    else if (lo == 1) sumsq = vB;
    else if (lo == 2) sumsq = vA + vC;
    else              sumsq = vA + vB;

    out[atom * (NDESC * LMAX) + lane] = 0.5f * (sumsq - ggv);
}

extern "C" void kernel_launch(void* const* d_in, const int* in_sizes, int n_in,
                              void* d_out, int out_size)
{
    const int*   types     = (const int*)d_in[0];
    const float* positions = (const float*)d_in[1];
    const int*   nbrs      = (const int*)d_in[2];
    const float* c_table   = (const float*)d_in[3];
    float*       out       = (float*)d_out;

    const int N = in_sizes[0];
    const int blocks = (N + WPB - 1) / WPB;
    angular_desc_kernel<<<blocks, THREADS>>>(types, positions, nbrs, c_table, out, N);
}

// round 7
// speedup vs baseline: 1.1859x; 1.1859x over previous
#include <cuda_runtime.h>

#define NTYPES 4
#define NDESC  8
#define KMAX   8
#define LMAX   4
#define MNBR   20
#define RCUT   5.0f
#define PI_F   3.14159265358979f

#define WPB     8
#define THREADS (WPB * 32)
#define CT_ROWS   (NTYPES * NTYPES)
#define CT_STRIDE 68                 // 68 % 32 == 4 -> conflict-free across type rows; 272B row, 16B aligned
#define REC_F4    7                  // edge record: 6 float4 used + 1 pad (STS conflict-free)
#define REC_F     (REC_F4 * 4)

__global__ __launch_bounds__(THREADS)
void angular_desc_kernel(const int*   __restrict__ types,
                         const float* __restrict__ positions,
                         const int*   __restrict__ nbrs,
                         const float* __restrict__ c_table,
                         float*       __restrict__ out,
                         int N)
{
    __shared__ float  sh_ct[CT_ROWS * CT_STRIDE];
    __shared__ float4 sh_e[WPB][MNBR][REC_F4];

    const int tid  = threadIdx.x;
    const int warp = tid >> 5;
    const int lane = tid & 31;
    const int atom = blockIdx.x * WPB + warp;
    const bool valid     = (atom < N);
    const bool edge_lane = valid && (lane < MNBR);

    // ---------------- issue the FULL dependent gmem chain first ----------------
    // (1) independent loads: neighbor index + own type/position
    int j = 0, ti = 0;
    float pix = 0.f, piy = 0.f, piz = 0.f;
    if (valid) {
        ti  = types[atom];
        pix = positions[atom * 3 + 0];
        piy = positions[atom * 3 + 1];
        piz = positions[atom * 3 + 2];
    }
    if (edge_lane) j = nbrs[atom * MNBR + lane];

    // (2) dependent loads: neighbor position + type (latency overlapped by staging below)
    float ejx = 0.f, ejy = 0.f, ejz = 0.f; int tj = 0;
    if (edge_lane) {
        ejx = positions[j * 3 + 0];
        ejy = positions[j * 3 + 1];
        ejz = positions[j * 3 + 2];
        tj  = types[j];
    }

    // ---------------- c_table staging: 1 LDG.128 + 1 STS.128 per thread ----------------
    {
        // 1024 floats = 256 float4; row = 16 float4s. Padded stride keeps 16B alignment.
        const float4 cv = ((const float4*)c_table)[tid];
        const int row = tid >> 4, col4 = tid & 15;
        *(float4*)&sh_ct[row * CT_STRIDE + col4 * 4] = cv;
    }
    __syncthreads();   // barrier wait also absorbs the tail of the gmem chain

    if (!valid) return;

    // ---------------- Phase 1: per-edge records (lanes 0..19): g[8] and Z[16] ----------------
    if (edge_lane) {
        float dx = ejx - pix;
        float dy = ejy - piy;
        float dz = ejz - piz;

        float n2  = dx * dx + dy * dy + dz * dz;
        float inv = rsqrtf(n2);
        float r   = n2 * inv;
        float x = dx * inv, y = dy * inv, z = dz * inv;

        // Chebyshev radial basis: f_k = (T_k(xc)+1) * 0.5*fc(r)
        float fc  = (r < RCUT) ? (0.5f * __cosf(PI_F * r * (1.0f / RCUT)) + 0.5f) : 0.0f;
        float hfc = 0.5f * fc;
        float xr  = r * (1.0f / RCUT) - 1.0f;
        float xc  = 2.0f * xr * xr - 1.0f;
        float fvec[KMAX];
        float tm2 = 1.0f, tm1 = xc;
        fvec[0] = (tm2 + 1.0f) * hfc;
        fvec[1] = (tm1 + 1.0f) * hfc;
        #pragma unroll
        for (int k = 2; k < KMAX; k++) {
            float t = 2.0f * xc * tm1 - tm2;
            tm2 = tm1; tm1 = t;
            fvec[k] = (t + 1.0f) * hfc;
        }

        const float* crow = &sh_ct[(ti * NTYPES + tj) * CT_STRIDE];
        float g[NDESC];
        #pragma unroll
        for (int d = 0; d < NDESC; d++) {
            const float4 c0 = *(const float4*)(crow + d * 8);
            const float4 c1 = *(const float4*)(crow + d * 8 + 4);
            g[d] = c0.x * fvec[0] + c0.y * fvec[1] + c0.z * fvec[2] + c0.w * fvec[3]
                 + c1.x * fvec[4] + c1.y * fvec[5] + c1.z * fvec[6] + c1.w * fvec[7];
        }

        // Real spherical harmonics Z_lm scaled so P_l(u.v) = sum_m Z_lm(u) Z_lm(v)
        float x2 = x * x, y2 = y * y, z2 = z * z;
        const float SQ3  = 1.73205080757f;
        const float SQ3H = 0.86602540378f;
        const float C31  = 0.61237243570f;   // sqrt(6)/4
        const float C32a = 3.87298334621f;   // sqrt(15)
        const float C32b = 1.93649167310f;   // sqrt(15)/2
        const float C33  = 0.79056941504f;   // sqrt(10)/4
        float a5z = 5.0f * z2 - 1.0f;

        sh_e[warp][lane][0] = make_float4(g[0], g[1], g[2], g[3]);
        sh_e[warp][lane][1] = make_float4(g[4], g[5], g[6], g[7]);
        sh_e[warp][lane][2] = make_float4(1.0f, x, y, z);
        sh_e[warp][lane][3] = make_float4(SQ3 * x * y, SQ3 * y * z, SQ3 * x * z, SQ3H * (x2 - y2));
        sh_e[warp][lane][4] = make_float4(0.5f * (3.0f * z2 - 1.0f),
                                          C33 * y * (3.0f * x2 - y2),
                                          C32a * x * y * z,
                                          C31 * y * a5z);
        sh_e[warp][lane][5] = make_float4(0.5f * z * (5.0f * z2 - 3.0f),
                                          C31 * x * a5z,
                                          C32b * z * (x2 - y2),
                                          C33 * x * (x2 - 3.0f * y2));
    }
    __syncwarp();

    // ---------------- Phase 2: S[d][m] = sum_j g_d(j) Z_m(j) ----------------
    const int d  = lane & 7;
    const int mg = lane >> 3;
    const float* rec = (const float*)&sh_e[warp][0][0];

    float S0 = 0.0f, S1 = 0.0f, S2 = 0.0f, S3 = 0.0f, gg = 0.0f;
    #pragma unroll
    for (int jb = 0; jb < MNBR; jb += 4) {
        float  gv[4];
        float4 zv[4];
        #pragma unroll
        for (int u = 0; u < 4; u++) {
            const float* base = rec + (jb + u) * REC_F;
            gv[u] = base[d];                              // broadcast within d-group
            zv[u] = *(const float4*)(base + 8 + 4 * mg);  // 4 distinct 16B: conflict-free
        }
        #pragma unroll
        for (int u = 0; u < 4; u++) {
            S0 = fmaf(gv[u], zv[u].x, S0);
            S1 = fmaf(gv[u], zv[u].y, S1);
            S2 = fmaf(gv[u], zv[u].z, S2);
            S3 = fmaf(gv[u], zv[u].w, S3);
            gg = fmaf(gv[u], gv[u], gg);
        }
    }

    // Sums of squares split by l within each m-group:
    // mg0: m0(l0) | m1..3(l1);  mg1: m4..7(l2);  mg2: m8(l2) | m9..11(l3);  mg3: m12..15(l3)
    float PA, PB;
    if (mg == 0 || mg == 2) {
        PA = S0 * S0;
        PB = S1 * S1 + S2 * S2 + S3 * S3;
    } else {
        PA = S0 * S0 + S1 * S1 + S2 * S2 + S3 * S3;
        PB = 0.0f;
    }

    // ---------------- Phase 3: recombine to output lane (od = lane>>2, lo = lane&3) ----------------
    const int lo = lane & 3;
    const int od = lane >> 2;

    int srcA = (lo == 0) ? od : (lo == 2) ? (8 + od) : (lo == 3) ? (24 + od) : od;
    float vA = __shfl_sync(0xffffffffu, PA, srcA);
    int srcB = (lo == 1) ? od : (16 + od);
    float vB = __shfl_sync(0xffffffffu, PB, srcB);
    float vC = __shfl_sync(0xffffffffu, PA, 16 + od);
    float ggv = __shfl_sync(0xffffffffu, gg, od);

    float sumsq;
    if      (lo == 0) sumsq = vA;
    else if (lo == 1) sumsq = vB;
    else if (lo == 2) sumsq = vA + vC;
    else              sumsq = vA + vB;

    out[atom * (NDESC * LMAX) + lane] = 0.5f * (sumsq - ggv);
}

extern "C" void kernel_launch(void* const* d_in, const int* in_sizes, int n_in,
                              void* d_out, int out_size)
{
    const int*   types     = (const int*)d_in[0];
    const float* positions = (const float*)d_in[1];
    const int*   nbrs      = (const int*)d_in[2];
    const float* c_table   = (const float*)d_in[3];
    float*       out       = (float*)d_out;

    const int N = in_sizes[0];
    const int blocks = (N + WPB - 1) / WPB;
    angular_desc_kernel<<<blocks, THREADS>>>(types, positions, nbrs, c_table, out, N);
}